// round 1
// baseline (speedup 1.0000x reference)
#include <cuda_runtime.h>
#include <cub/cub.cuh>

#define HW    64
#define NPIX  4096
#define NTASK 24
#define BT    512
#define IPT   8

struct TaskRes { double s2; float pmax; float vfirst; int has; };
__device__ TaskRes g_res[NTASK];

typedef cub::BlockRadixSort<unsigned long long, BT, IPT> Sorter;

struct UFArrays {
    float          vals[NPIX];    // filtration values (negated for superlevel run)
    short          parent[NPIX];  // -1 = not yet inserted
    unsigned short rank[NPIX];    // insertion order (birth rank of node)
};

union Region {
    typename Sorter::TempStorage sort;
    UFArrays                     uf;
};

__global__ __launch_bounds__(BT) void uf_kernel(const float* __restrict__ x)
{
    __shared__ unsigned short s_order[NPIX];
    __shared__ Region         reg;
    __shared__ volatile int   s_nb[8];

    const int task    = blockIdx.x;
    const int img     = task >> 1;
    const int variant = task & 1;          // 0: sublevel v, 8-conn ; 1: sublevel -v, 4-conn
    const int b       = img / 3;
    const int c       = img % 3 + 1;       // skip background class 0
    const float* v    = x + (size_t)(b * 4 + c) * NPIX;

    // ---- build 44-bit keys: (monotone float bits)<<12 | pixel index -------
    unsigned long long keys[IPT];
#pragma unroll
    for (int i = 0; i < IPT; i++) {
        int p = threadIdx.x * IPT + i;
        unsigned int bits = __float_as_uint(v[p]);   // v in [0,1): bits monotone
        if (variant) bits = ~bits;                   // descending v, ties idx asc
        keys[i] = ((unsigned long long)bits << 12) | (unsigned)p;
    }
    Sorter(reg.sort).Sort(keys, 0, 44);
#pragma unroll
    for (int i = 0; i < IPT; i++)
        s_order[threadIdx.x * IPT + i] = (unsigned short)(keys[i] & 0xFFFu);
    __syncthreads();

    // ---- init UF arrays (reuses the sort temp storage region) -------------
#pragma unroll
    for (int i = 0; i < IPT; i++) {
        int p = threadIdx.x * IPT + i;
        float val = v[p];
        reg.uf.vals[p]   = variant ? -val : val;
        reg.uf.parent[p] = -1;
    }
    __syncthreads();

    // ---- warp 0: sequential elder-rule union-find in shared memory --------
    if (threadIdx.x < 32) {
        volatile short*  par  = reg.uf.parent;
        const float*     vals = reg.uf.vals;
        unsigned short*  rk   = reg.uf.rank;
        const int lane = threadIdx.x;
        const int drs[8] = {-1, 1, 0, 0, -1, -1, 1, 1};
        const int dcs[8] = { 0, 0,-1, 1, -1,  1,-1, 1};
        const int nOff = variant ? 4 : 8;

        double S2   = 0.0;
        float  pmax = 0.0f;
        int    has  = 0;

        for (int t = 0; t < NPIX; t++) {
            const int idx = s_order[t];
            if (lane == 0) { par[idx] = (short)idx; rk[idx] = (unsigned short)t; }
            __syncwarp();

            // phase 1: lanes identify inserted neighbors + pre-compress paths
            if (lane < nOff) {
                int r  = idx >> 6, cc = idx & 63;
                int rr = r + drs[lane], c2 = cc + dcs[lane];
                int nb = -1;
                if (rr >= 0 && rr < HW && c2 >= 0 && c2 < HW) {
                    int q = rr * HW + c2;
                    if (par[q] >= 0) {
                        nb = q;
                        int a = q, p = par[a];
                        while (p != a) {        // path halving (benign races)
                            int g = par[p];
                            par[a] = (short)g;
                            a = g; p = par[a];
                        }
                    }
                }
                s_nb[lane] = nb;
            }
            __syncwarp();

            // phase 2: lane 0 does the sequential merges in reference order
            if (lane == 0) {
                const float vi = vals[idx];
                for (int j = 0; j < nOff; j++) {
                    int q = s_nb[j];
                    if (q < 0) continue;
                    int ra = idx;
                    { int p = par[ra]; while (p != ra) { int g = par[p]; par[ra] = (short)g; ra = g; p = par[ra]; } }
                    int rb = q;
                    { int p = par[rb]; while (p != rb) { int g = par[p]; par[rb] = (short)g; rb = g; p = par[rb]; } }
                    if (ra != rb) {
                        int elder, young;
                        if (rk[ra] < rk[rb]) { elder = ra; young = rb; }
                        else                 { elder = rb; young = ra; }
                        float vy = vals[young];     // root == its own creator
                        if (vi > vy) {              // drop 0-persistence pairs
                            float p = vi - vy;
                            S2 += (double)p * (double)p;
                            if (p > pmax) pmax = p;
                            has = 1;
                        }
                        par[young] = (short)elder;
                    }
                }
            }
            __syncwarp();
        }

        if (lane == 0) {
            TaskRes r;
            r.s2 = S2; r.pmax = pmax; r.has = has;
            r.vfirst = vals[s_order[0]];   // essential birth value (sublevel run)
            g_res[task] = r;
        }
    }
}

__global__ void loss_kernel(float* __restrict__ out)
{
    // per class c=1,2,3: extra finite kept pairs in H0 beyond essential; nf for H1
    const int nf_extra_h0[3] = {0, 0, 1};
    const int nf_h1[3]       = {0, 1, 0};
    double loss = 0.0;
    for (int img = 0; img < 12; img++) {
        const int ci = img % 3;
        TaskRes sub = g_res[img * 2];
        TaskRes sup = g_res[img * 2 + 1];

        // H0: essential kept -> (1-(1-v_ess))^2 = v_ess^2 ; all finite pairs pers^2
        double h0 = (double)sub.vfirst * (double)sub.vfirst + sub.s2;
        if (nf_extra_h0[ci]) {
            if (sub.has) { double p = sub.pmax; h0 += (1.0 - p) * (1.0 - p) - p * p; }
            else          h0 += 1.0;   // missing feature
        }
        // H1: all pairs pers^2 ; class 2 keeps the max-persistence pair
        double h1 = sup.s2;
        if (nf_h1[ci]) {
            if (sup.has) { double p = sup.pmax; h1 += (1.0 - p) * (1.0 - p) - p * p; }
            else          h1 += 1.0;
        }
        loss += h0 + h1;
    }
    out[0] = (float)(loss * 0.25);   // divide by B = 4
}

extern "C" void kernel_launch(void* const* d_in, const int* in_sizes, int n_in,
                              void* d_out, int out_size)
{
    (void)in_sizes; (void)n_in; (void)out_size;
    const float* x = (const float*)d_in[0];
    uf_kernel<<<NTASK, BT>>>(x);
    loss_kernel<<<1, 1>>>((float*)d_out);
}

// round 2
// speedup vs baseline: 2.4470x; 2.4470x over previous
#include <cuda_runtime.h>
#include <cub/cub.cuh>

#define HW    64
#define NPIX  4096
#define NTASK 24
#define BT    512
#define IPT   8

struct TaskRes { double s2; float pmax; float vfirst; int has; };
__device__ TaskRes g_res[NTASK];

typedef cub::BlockRadixSort<unsigned long long, BT, IPT> Sorter;

struct ShmA {
    unsigned short rank[NPIX];   // rank by vertex
    unsigned short F[NPIX];      // basin root (local min) by vertex
    float          val[NPIX];    // filtration value (negated for variant 1)
    unsigned short mpar[NPIX];   // minima union-find parent
};

struct Shm {
    union { typename Sorter::TempStorage sort; ShmA a; } u;
    unsigned short order[NPIX];  // vertices by rank; reused as candidate list
    int wsum[16];
    int ncand;
};

__device__ __forceinline__ int mfind(unsigned short* mpar, int a) {
    int root = a, p = mpar[root];
    while (p != root) { root = p; p = mpar[root]; }
    while (mpar[a] != (unsigned short)root) {
        int n = mpar[a]; mpar[a] = (unsigned short)root; a = n;
    }
    return root;
}

__global__ __launch_bounds__(BT) void uf_kernel(const float* __restrict__ x)
{
    extern __shared__ char raw[];
    Shm& sh = *(Shm*)raw;

    const int task    = blockIdx.x;
    const int img     = task >> 1;
    const int variant = task & 1;          // 0: sublevel v (8-conn); 1: sublevel -v (4-conn)
    const int b       = img / 3;
    const int c       = img % 3 + 1;
    const float* v    = x + (size_t)(b * 4 + c) * NPIX;
    const int tid     = threadIdx.x;
    const int nOff    = variant ? 4 : 8;

    const int drs[8] = {-1, 1, 0, 0, -1, -1, 1, 1};
    const int dcs[8] = { 0, 0,-1, 1, -1,  1,-1, 1};

    // ---- 44-bit keys: monotone float bits << 12 | pixel idx (stable ties) --
    unsigned long long keys[IPT];
    float vloc[IPT];
#pragma unroll
    for (int i = 0; i < IPT; i++) {
        int p = tid * IPT + i;
        float val = v[p];
        vloc[i] = variant ? -val : val;
        unsigned bits = __float_as_uint(val);   // v in [0,1): monotone
        if (variant) bits = ~bits;              // descending v, ties idx asc
        keys[i] = ((unsigned long long)bits << 12) | (unsigned)p;
    }
    Sorter(sh.u.sort).Sort(keys, 0, 44);
    __syncthreads();                            // retire sort temp storage

    // ---- order / rank / val / mpar ----------------------------------------
#pragma unroll
    for (int i = 0; i < IPT; i++) {
        int t   = tid * IPT + i;
        int idx = (int)(keys[i] & 0xFFFu);
        sh.order[t]        = (unsigned short)idx;
        sh.u.a.rank[idx]   = (unsigned short)t;
        int p = tid * IPT + i;
        sh.u.a.val[p]  = vloc[i];
        sh.u.a.mpar[p] = (unsigned short)p;
    }
    __syncthreads();

    // ---- steepest-descent pointer: min-rank strictly-lower neighbor -------
#pragma unroll
    for (int i = 0; i < IPT; i++) {
        int p = tid * IPT + i;
        int r = p >> 6, cc = p & 63;
        int best = p, bestr = sh.u.a.rank[p];
        for (int k = 0; k < nOff; k++) {
            int rr = r + drs[k], c2 = cc + dcs[k];
            if (rr >= 0 && rr < HW && c2 >= 0 && c2 < HW) {
                int q  = rr * HW + c2;
                int rq = sh.u.a.rank[q];
                if (rq < bestr) { bestr = rq; best = q; }
            }
        }
        sh.u.a.F[p] = (unsigned short)best;
    }
    __syncthreads();

    // ---- pointer jumping: F becomes the basin's local minimum -------------
    for (int round = 0; round < 13; round++) {
#pragma unroll
        for (int i = 0; i < IPT; i++) {
            int p = tid * IPT + i;
            int f = sh.u.a.F[p];
            sh.u.a.F[p] = sh.u.a.F[f];          // benign races: only jump forward
        }
        __syncthreads();
    }

    // ---- candidate saddles: lower nbrs span >=2 distinct basins -----------
    int cnt = 0;
    unsigned short cidx[IPT];
#pragma unroll
    for (int i = 0; i < IPT; i++) {
        int t   = tid * IPT + i;
        int idx = sh.order[t];
        int r = idx >> 6, cc = idx & 63;
        int r0 = -1; bool cand = false;
        for (int k = 0; k < nOff; k++) {
            int rr = r + drs[k], c2 = cc + dcs[k];
            if (rr >= 0 && rr < HW && c2 >= 0 && c2 < HW) {
                int q = rr * HW + c2;
                if (sh.u.a.rank[q] < t) {
                    int f = sh.u.a.F[q];
                    if (r0 < 0) r0 = f;
                    else if (f != r0) cand = true;
                }
            }
        }
        if (cand) cidx[cnt++] = (unsigned short)idx;
    }
    float vfirst = 0.f;
    if (tid == 0) vfirst = sh.u.a.val[sh.order[0]];   // essential birth (global min)
    __syncthreads();                                   // all order[] reads done

    // ---- rank-ordered compaction into sh.order (warp scan) ----------------
    const int lane = tid & 31, warp = tid >> 5;
    int incl = cnt;
#pragma unroll
    for (int d = 1; d < 32; d <<= 1) {
        int n = __shfl_up_sync(0xFFFFFFFFu, incl, d);
        if (lane >= d) incl += n;
    }
    if (lane == 31) sh.wsum[warp] = incl;
    __syncthreads();
    if (tid == 0) {
        int s = 0;
        for (int w = 0; w < 16; w++) { int t = sh.wsum[w]; sh.wsum[w] = s; s += t; }
        sh.ncand = s;
    }
    __syncthreads();
    int base = sh.wsum[warp] + incl - cnt;
    for (int i = 0; i < cnt; i++) sh.order[base + i] = cidx[i];
    __syncthreads();

    // ---- sequential elder-rule UF over local minima only ------------------
    if (tid == 0) {
        unsigned short*       mpar = sh.u.a.mpar;
        const unsigned short* rank = sh.u.a.rank;
        const unsigned short* F    = sh.u.a.F;
        const float*          val  = sh.u.a.val;
        const unsigned short* cand = sh.order;
        const int ncand = sh.ncand;

        double S2 = 0.0; float pmax = 0.f; int has = 0;

        for (int j = 0; j < ncand; j++) {
            int idx = cand[j];
            int ti  = rank[idx];
            float vi = val[idx];
            int r = idx >> 6, cc = idx & 63;
            int roots[8]; int nr = 0;
            for (int k = 0; k < nOff; k++) {
                int rr = r + drs[k], c2 = cc + dcs[k];
                if (rr >= 0 && rr < HW && c2 >= 0 && c2 < HW) {
                    int q = rr * HW + c2;
                    if (rank[q] < ti) roots[nr++] = F[q];
                }
            }
            int cur = -1;
            for (int k = 0; k < nr; k++) {
                int root = mfind(mpar, roots[k]);
                if (root == cur) continue;
                if (cur < 0) { cur = root; continue; }
                int e, y;
                if (rank[root] < rank[cur]) { e = root; y = cur; }
                else                        { e = cur;  y = root; }
                float p = vi - val[y];                 // birth = loser root's value
                if (p > 0.f) {                         // strictly positive persistence
                    S2 += (double)p * (double)p;
                    if (p > pmax) pmax = p;
                    has = 1;
                }
                mpar[y] = (unsigned short)e;
                cur = e;
            }
        }

        TaskRes res;
        res.s2 = S2; res.pmax = pmax; res.has = has; res.vfirst = vfirst;
        g_res[task] = res;
    }
}

__global__ void loss_kernel(float* __restrict__ out)
{
    const int nf_extra_h0[3] = {0, 0, 1};
    const int nf_h1[3]       = {0, 1, 0};
    double loss = 0.0;
    for (int img = 0; img < 12; img++) {
        const int ci = img % 3;
        TaskRes sub = g_res[img * 2];
        TaskRes sup = g_res[img * 2 + 1];

        double h0 = (double)sub.vfirst * (double)sub.vfirst + sub.s2;
        if (nf_extra_h0[ci]) {
            if (sub.has) { double p = sub.pmax; h0 += (1.0 - p) * (1.0 - p) - p * p; }
            else          h0 += 1.0;
        }
        double h1 = sup.s2;
        if (nf_h1[ci]) {
            if (sup.has) { double p = sup.pmax; h1 += (1.0 - p) * (1.0 - p) - p * p; }
            else          h1 += 1.0;
        }
        loss += h0 + h1;
    }
    out[0] = (float)(loss * 0.25);
}

extern "C" void kernel_launch(void* const* d_in, const int* in_sizes, int n_in,
                              void* d_out, int out_size)
{
    (void)in_sizes; (void)n_in; (void)out_size;
    const float* x = (const float*)d_in[0];
    cudaFuncSetAttribute(uf_kernel, cudaFuncAttributeMaxDynamicSharedMemorySize,
                         (int)sizeof(Shm));
    uf_kernel<<<NTASK, BT, sizeof(Shm)>>>(x);
    loss_kernel<<<1, 1>>>((float*)d_out);
}

// round 3
// speedup vs baseline: 29.7001x; 12.1373x over previous
#include <cuda_runtime.h>
#include <cub/cub.cuh>

#define HW       64
#define NPIX     4096
#define NTASK    24
#define BT       512
#define IPT      8
#define EDGE_CAP 12288

struct TaskRes { double s2; float pmax; float vfirst; int has; };
__device__ TaskRes g_res[NTASK];

// stable radix sort: 32-bit monotone float keys, u16 pixel-index values
typedef cub::BlockRadixSort<unsigned int, BT, IPT, unsigned short> Sorter;

struct ShmA {
    unsigned short rank[NPIX];   // rank by vertex
    unsigned short F[NPIX];      // basin root (local min) by vertex
    float          val[NPIX];    // filtration value (negated for variant 1)
    unsigned short mpar[NPIX];   // minima union-find parent
};

struct Shm {
    union { typename Sorter::TempStorage sort; ShmA a; } u;
    unsigned short     order[NPIX];       // vertices by rank
    unsigned long long edges[EDGE_CAP];   // (valbits<<24)|(a<<12)|b, rank-ordered
    int wsum[16];
    int ne;
};

__global__ __launch_bounds__(BT) void uf_kernel(const float* __restrict__ x)
{
    extern __shared__ char raw[];
    Shm& sh = *(Shm*)raw;

    const int task    = blockIdx.x;
    const int img     = task >> 1;
    const int variant = task & 1;          // 0: sublevel v (8-conn); 1: sublevel -v (4-conn)
    const int b       = img / 3;
    const int c       = img % 3 + 1;
    const float* v    = x + (size_t)(b * 4 + c) * NPIX;
    const int tid     = threadIdx.x;
    const int nOff    = variant ? 4 : 8;

    const int drs[8] = {-1, 1, 0, 0, -1, -1, 1, 1};
    const int dcs[8] = { 0, 0,-1, 1, -1,  1,-1, 1};

    // ---- stable sort: key = (maybe complemented) float bits, value = idx ---
    unsigned int   keys[IPT];
    unsigned short idxs[IPT];
    float vloc[IPT];
#pragma unroll
    for (int i = 0; i < IPT; i++) {
        int p = tid * IPT + i;
        float val = v[p];
        vloc[i] = variant ? -val : val;
        unsigned bits = __float_as_uint(val);    // v in [0,1): bits monotone
        keys[i] = variant ? ~bits : bits;        // variant 1: descending v, stable ties
        idxs[i] = (unsigned short)p;
    }
    Sorter(sh.u.sort).Sort(keys, idxs);
    __syncthreads();                             // retire sort temp storage

    // ---- order / rank / val / mpar ----------------------------------------
#pragma unroll
    for (int i = 0; i < IPT; i++) {
        int t   = tid * IPT + i;
        int idx = idxs[i];
        sh.order[t]      = (unsigned short)idx;
        sh.u.a.rank[idx] = (unsigned short)t;
        int p = tid * IPT + i;
        sh.u.a.val[p]  = vloc[i];
        sh.u.a.mpar[p] = (unsigned short)p;
    }
    __syncthreads();

    // ---- steepest-descent pointer: min-rank strictly-lower neighbor -------
#pragma unroll
    for (int i = 0; i < IPT; i++) {
        int p = tid * IPT + i;
        int r = p >> 6, cc = p & 63;
        int best = p, bestr = sh.u.a.rank[p];
        for (int k = 0; k < nOff; k++) {
            int rr = r + drs[k], c2 = cc + dcs[k];
            if (rr >= 0 && rr < HW && c2 >= 0 && c2 < HW) {
                int q  = rr * HW + c2;
                int rq = sh.u.a.rank[q];
                if (rq < bestr) { bestr = rq; best = q; }
            }
        }
        sh.u.a.F[p] = (unsigned short)best;
    }
    __syncthreads();

    // ---- pointer jumping: F becomes the basin's local minimum -------------
    for (int round = 0; round < 13; round++) {
#pragma unroll
        for (int i = 0; i < IPT; i++) {
            int p = tid * IPT + i;
            int f = sh.u.a.F[p];
            sh.u.a.F[p] = sh.u.a.F[f];           // benign forward-jump races
        }
        __syncthreads();
    }

    // ---- pass 1: count edges per thread (rank-ordered) --------------------
    int cnt = 0;
#pragma unroll
    for (int i = 0; i < IPT; i++) {
        int t   = tid * IPT + i;
        int idx = sh.order[t];
        int r = idx >> 6, cc = idx & 63;
        unsigned short fs[8]; int nf = 0;
        for (int k = 0; k < nOff; k++) {
            int rr = r + drs[k], c2 = cc + dcs[k];
            if (rr >= 0 && rr < HW && c2 >= 0 && c2 < HW) {
                int q = rr * HW + c2;
                if (sh.u.a.rank[q] < t) {
                    unsigned short f = sh.u.a.F[q];
                    bool dup = false;
                    for (int j = 0; j < nf; j++) if (fs[j] == f) dup = true;
                    if (!dup) fs[nf++] = f;
                }
            }
        }
        if (nf >= 2) cnt += nf - 1;
    }

    // ---- block-exclusive scan over edge counts ----------------------------
    const int lane = tid & 31, warp = tid >> 5;
    int incl = cnt;
#pragma unroll
    for (int d = 1; d < 32; d <<= 1) {
        int n = __shfl_up_sync(0xFFFFFFFFu, incl, d);
        if (lane >= d) incl += n;
    }
    if (lane == 31) sh.wsum[warp] = incl;
    __syncthreads();
    if (tid == 0) {
        int s = 0;
        for (int w = 0; w < 16; w++) { int t = sh.wsum[w]; sh.wsum[w] = s; s += t; }
        sh.ne = (s > EDGE_CAP) ? EDGE_CAP : s;
    }
    __syncthreads();
    int pos = sh.wsum[warp] + incl - cnt;

    // ---- pass 2: emit edges (r1, ri) with saddle value --------------------
#pragma unroll
    for (int i = 0; i < IPT; i++) {
        int t   = tid * IPT + i;
        int idx = sh.order[t];
        int r = idx >> 6, cc = idx & 63;
        unsigned short fs[8]; int nf = 0;
        for (int k = 0; k < nOff; k++) {
            int rr = r + drs[k], c2 = cc + dcs[k];
            if (rr >= 0 && rr < HW && c2 >= 0 && c2 < HW) {
                int q = rr * HW + c2;
                if (sh.u.a.rank[q] < t) {
                    unsigned short f = sh.u.a.F[q];
                    bool dup = false;
                    for (int j = 0; j < nf; j++) if (fs[j] == f) dup = true;
                    if (!dup) fs[nf++] = f;
                }
            }
        }
        if (nf >= 2) {
            unsigned long long vb =
                ((unsigned long long)__float_as_uint(sh.u.a.val[idx]) << 24) |
                ((unsigned long long)fs[0] << 12);
            for (int j = 1; j < nf; j++) {
                if (pos < EDGE_CAP) sh.edges[pos] = vb | fs[j];
                pos++;
            }
        }
    }
    __syncthreads();

    // ---- warp 0: speculative-parallel Kruskal over minima -----------------
    if (tid < 32) {
        unsigned short*       mpar = sh.u.a.mpar;
        const unsigned short* rank = sh.u.a.rank;
        const float*          val  = sh.u.a.val;
        const int ne = sh.ne;

        double S2 = 0.0; float pmax = 0.f; int has = 0;

        for (int base = 0; base < ne; base += 32) {
            int e = base + lane;
            int fa = 0, fb = 0; float vv = 0.f; bool act = false;
            if (e < ne) {
                unsigned long long rec = sh.edges[e];
                int a = (int)((rec >> 12) & 0xFFFu);
                int bb = (int)(rec & 0xFFFu);
                vv = __uint_as_float((unsigned)(rec >> 24));
                fa = a;
                while (mpar[fa] != fa) { unsigned short g = mpar[mpar[fa]]; mpar[fa] = g; fa = g; }
                fb = bb;
                while (mpar[fb] != fb) { unsigned short g = mpar[mpar[fb]]; mpar[fb] = g; fb = g; }
                act = (fa != fb);           // fa==fb can never merge later: skip forever
            }
            unsigned mask = __ballot_sync(0xFFFFFFFFu, act);
            __syncwarp();
            while (mask) {                  // serial commit in rank order
                int src = __ffs(mask) - 1; mask &= mask - 1;
                int   xa = __shfl_sync(0xFFFFFFFFu, fa, src);
                int   xb = __shfl_sync(0xFFFFFFFFu, fb, src);
                float xv = __shfl_sync(0xFFFFFFFFu, vv, src);
                if (lane == 0) {
                    int ra = xa;
                    while (mpar[ra] != ra) { unsigned short g = mpar[mpar[ra]]; mpar[ra] = g; ra = g; }
                    int rb = xb;
                    while (mpar[rb] != rb) { unsigned short g = mpar[mpar[rb]]; mpar[rb] = g; rb = g; }
                    if (ra != rb) {
                        int eld, yng;
                        if (rank[ra] < rank[rb]) { eld = ra; yng = rb; }
                        else                     { eld = rb; yng = ra; }
                        float p = xv - val[yng];       // birth = loser root's value
                        if (p > 0.f) {
                            S2 += (double)p * (double)p;
                            if (p > pmax) pmax = p;
                            has = 1;
                        }
                        mpar[yng] = (unsigned short)eld;
                    }
                }
            }
            __syncwarp();
        }

        if (lane == 0) {
            TaskRes r;
            r.s2 = S2; r.pmax = pmax; r.has = has;
            r.vfirst = sh.u.a.val[sh.order[0]];   // essential birth (global min)
            g_res[task] = r;
        }
    }
}

__global__ void loss_kernel(float* __restrict__ out)
{
    const int nf_extra_h0[3] = {0, 0, 1};
    const int nf_h1[3]       = {0, 1, 0};
    double loss = 0.0;
    for (int img = 0; img < 12; img++) {
        const int ci = img % 3;
        TaskRes sub = g_res[img * 2];
        TaskRes sup = g_res[img * 2 + 1];

        double h0 = (double)sub.vfirst * (double)sub.vfirst + sub.s2;
        if (nf_extra_h0[ci]) {
            if (sub.has) { double p = sub.pmax; h0 += (1.0 - p) * (1.0 - p) - p * p; }
            else          h0 += 1.0;
        }
        double h1 = sup.s2;
        if (nf_h1[ci]) {
            if (sup.has) { double p = sup.pmax; h1 += (1.0 - p) * (1.0 - p) - p * p; }
            else          h1 += 1.0;
        }
        loss += h0 + h1;
    }
    out[0] = (float)(loss * 0.25);
}

extern "C" void kernel_launch(void* const* d_in, const int* in_sizes, int n_in,
                              void* d_out, int out_size)
{
    (void)in_sizes; (void)n_in; (void)out_size;
    const float* x = (const float*)d_in[0];
    cudaFuncSetAttribute(uf_kernel, cudaFuncAttributeMaxDynamicSharedMemorySize,
                         (int)sizeof(Shm));
    uf_kernel<<<NTASK, BT, sizeof(Shm)>>>(x);
    loss_kernel<<<1, 1>>>((float*)d_out);
}

// round 5
// speedup vs baseline: 52.2579x; 1.7595x over previous
#include <cuda_runtime.h>
#include <cub/cub.cuh>

#define HW       64
#define NPIX     4096
#define NTASK    24
#define BT       1024
#define IPT      4
#define EDGE_CAP 12288
#define FULL     0xFFFFFFFFu

struct TaskRes { double s2; float pmax; float vfirst; int has; };
__device__ TaskRes g_res[NTASK];
__device__ unsigned g_ctr = 0;   // self-resetting completion counter

// stable radix sort: 30-bit monotone keys, u16 pixel-index values, 6 passes
// RADIX_BITS=5 keeps ranking temp ~70KB (6 bits @ BT=1024 blew the 227KB limit)
typedef cub::BlockRadixSort<unsigned int, BT, IPT, unsigned short, 5> Sorter;

struct ShmA {
    unsigned short rank[NPIX];   // rank by vertex
    unsigned short F[NPIX];      // basin root (local min) by vertex
    float          val[NPIX];    // filtration value (negated for variant 1)
    unsigned short mpar[NPIX];   // minima union-find parent
};

struct Shm {
    union { typename Sorter::TempStorage sort; ShmA a; } u;
    unsigned short     order[NPIX];       // vertices by rank
    unsigned long long edges[EDGE_CAP];   // (valbits<<24)|(a<<12)|b, rank-ordered
    unsigned           claim[NPIX];       // endpoint claims for parallel commit
    int wsum[32];
    int ne;
};

__device__ __forceinline__ int phfind(unsigned short* mpar, int a) {
    int p = mpar[a];
    while (p != a) {                       // path halving
        int g = mpar[p];
        mpar[a] = (unsigned short)g;
        a = g; p = mpar[a];
    }
    return a;
}

__global__ __launch_bounds__(BT) void uf_kernel(const float* __restrict__ x,
                                                float* __restrict__ out)
{
    extern __shared__ char raw[];
    Shm& sh = *(Shm*)raw;

    const int task    = blockIdx.x;
    const int img     = task >> 1;
    const int variant = task & 1;          // 0: sublevel v (8-conn); 1: sublevel -v (4-conn)
    const int b       = img / 3;
    const int c       = img % 3 + 1;
    const float* v    = x + (size_t)(b * 4 + c) * NPIX;
    const int tid     = threadIdx.x;
    const int nOff    = variant ? 4 : 8;

    const int drs[8] = {-1, 1, 0, 0, -1, -1, 1, 1};
    const int dcs[8] = { 0, 0,-1, 1, -1,  1,-1, 1};

    // ---- stable sort: 30-bit keys (v in [0,1) -> bits < 2^30) --------------
    unsigned int   keys[IPT];
    unsigned short idxs[IPT];
    float vloc[IPT];
#pragma unroll
    for (int i = 0; i < IPT; i++) {
        int p = tid * IPT + i;
        float val = v[p];
        vloc[i] = variant ? -val : val;
        unsigned bits = __float_as_uint(val);             // monotone for v >= 0
        keys[i] = (variant ? ~bits : bits) & 0x3FFFFFFFu; // var1: desc v, stable ties
        idxs[i] = (unsigned short)p;
    }
    Sorter(sh.u.sort).Sort(keys, idxs, 0, 30);
    __syncthreads();                                      // retire sort temp storage

    // ---- order / rank / val / mpar / claim ---------------------------------
#pragma unroll
    for (int i = 0; i < IPT; i++) {
        int t   = tid * IPT + i;
        int idx = idxs[i];
        sh.order[t]      = (unsigned short)idx;
        sh.u.a.rank[idx] = (unsigned short)t;
        int p = tid * IPT + i;
        sh.u.a.val[p]  = vloc[i];
        sh.u.a.mpar[p] = (unsigned short)p;
        sh.claim[p]    = FULL;
    }
    __syncthreads();

    // ---- steepest-descent pointer: min-rank strictly-lower neighbor --------
#pragma unroll
    for (int i = 0; i < IPT; i++) {
        int p = tid * IPT + i;
        int r = p >> 6, cc = p & 63;
        int best = p, bestr = sh.u.a.rank[p];
        for (int k = 0; k < nOff; k++) {
            int rr = r + drs[k], c2 = cc + dcs[k];
            if (rr >= 0 && rr < HW && c2 >= 0 && c2 < HW) {
                int q  = rr * HW + c2;
                int rq = sh.u.a.rank[q];
                if (rq < bestr) { bestr = rq; best = q; }
            }
        }
        sh.u.a.F[p] = (unsigned short)best;
    }
    __syncthreads();

    // ---- pointer jumping until converged (benign forward-jump races) -------
    int changed = 1;
    while (__syncthreads_or(changed)) {
        changed = 0;
#pragma unroll
        for (int i = 0; i < IPT; i++) {
            int p = tid * IPT + i;
            int f = sh.u.a.F[p];
            int g = sh.u.a.F[f];
            if (g != f) { sh.u.a.F[p] = (unsigned short)g; changed = 1; }
        }
    }

    // ---- pass 1: count edges per thread (rank order) -----------------------
    int cnt = 0;
#pragma unroll
    for (int i = 0; i < IPT; i++) {
        int t   = tid * IPT + i;
        int idx = sh.order[t];
        int r = idx >> 6, cc = idx & 63;
        unsigned short fs[8]; int nf = 0;
        for (int k = 0; k < nOff; k++) {
            int rr = r + drs[k], c2 = cc + dcs[k];
            if (rr >= 0 && rr < HW && c2 >= 0 && c2 < HW) {
                int q = rr * HW + c2;
                if (sh.u.a.rank[q] < t) {
                    unsigned short f = sh.u.a.F[q];
                    bool dup = false;
                    for (int j = 0; j < nf; j++) if (fs[j] == f) dup = true;
                    if (!dup) fs[nf++] = f;
                }
            }
        }
        if (nf >= 2) cnt += nf - 1;
    }

    // ---- block-exclusive scan over edge counts -----------------------------
    const int lane = tid & 31, warp = tid >> 5;
    int incl = cnt;
#pragma unroll
    for (int d = 1; d < 32; d <<= 1) {
        int n = __shfl_up_sync(FULL, incl, d);
        if (lane >= d) incl += n;
    }
    if (lane == 31) sh.wsum[warp] = incl;
    __syncthreads();
    if (tid == 0) {
        int s = 0;
        for (int w = 0; w < 32; w++) { int t = sh.wsum[w]; sh.wsum[w] = s; s += t; }
        sh.ne = (s > EDGE_CAP) ? EDGE_CAP : s;
    }
    __syncthreads();
    int pos = sh.wsum[warp] + incl - cnt;

    // ---- pass 2: emit edges (r1, ri) with saddle value ---------------------
#pragma unroll
    for (int i = 0; i < IPT; i++) {
        int t   = tid * IPT + i;
        int idx = sh.order[t];
        int r = idx >> 6, cc = idx & 63;
        unsigned short fs[8]; int nf = 0;
        for (int k = 0; k < nOff; k++) {
            int rr = r + drs[k], c2 = cc + dcs[k];
            if (rr >= 0 && rr < HW && c2 >= 0 && c2 < HW) {
                int q = rr * HW + c2;
                if (sh.u.a.rank[q] < t) {
                    unsigned short f = sh.u.a.F[q];
                    bool dup = false;
                    for (int j = 0; j < nf; j++) if (fs[j] == f) dup = true;
                    if (!dup) fs[nf++] = f;
                }
            }
        }
        if (nf >= 2) {
            unsigned long long vb =
                ((unsigned long long)__float_as_uint(sh.u.a.val[idx]) << 24) |
                ((unsigned long long)fs[0] << 12);
            for (int j = 1; j < nf; j++) {
                if (pos < EDGE_CAP) sh.edges[pos] = vb | fs[j];
                pos++;
            }
        }
    }
    __syncthreads();

    // ---- warp 0: parallel-commit Kruskal over minima -----------------------
    if (tid < 32) {
        unsigned short*       mpar  = sh.u.a.mpar;
        const unsigned short* rank  = sh.u.a.rank;
        const float*          val   = sh.u.a.val;
        unsigned*             claim = sh.claim;
        const int ne = sh.ne;

        double S2 = 0.0; float pmax = 0.f; int has = 0;

        for (int base = 0; base < ne; base += 32) {
            int e = base + lane;
            int fa = 0, fb = 0; float vv = 0.f;
            bool act = (e < ne);
            if (act) {
                unsigned long long rec = sh.edges[e];
                fa = (int)((rec >> 12) & 0xFFFu);
                fb = (int)(rec & 0xFFFu);
                vv = __uint_as_float((unsigned)(rec >> 24));
            }
            unsigned act_mask = __ballot_sync(FULL, act);
            while (act_mask) {
                // re-find roots (concurrent path halving: benign races)
                if (act) {
                    fa = phfind(mpar, fa);
                    fb = phfind(mpar, fb);
                    if (fa == fb) act = false;   // can never merge: skip forever
                }
                __syncwarp();
                // claim endpoints; lowest lane (= earliest edge) wins
                if (act) {
                    atomicMin(&claim[fa], (unsigned)lane);
                    atomicMin(&claim[fb], (unsigned)lane);
                }
                __syncwarp();
                bool win = act && claim[fa] == (unsigned)lane
                               && claim[fb] == (unsigned)lane;
                __syncwarp();                    // all claim reads done
                if (act) { claim[fa] = FULL; claim[fb] = FULL; }
                if (win) {                       // disjoint root pairs: commit in parallel
                    int eld, yng;
                    if (rank[fa] < rank[fb]) { eld = fa; yng = fb; }
                    else                     { eld = fb; yng = fa; }
                    float p = vv - val[yng];     // birth = loser root's value
                    if (p > 0.f) {
                        S2 += (double)p * (double)p;
                        if (p > pmax) pmax = p;
                        has = 1;
                    }
                    mpar[yng] = (unsigned short)eld;
                    act = false;
                }
                __syncwarp();                    // commits visible before next refind
                act_mask = __ballot_sync(FULL, act);
            }
        }

        // warp reduction (deterministic order)
#pragma unroll
        for (int off = 16; off; off >>= 1) {
            S2 += __shfl_down_sync(FULL, S2, off);
            float pm = __shfl_down_sync(FULL, pmax, off);
            pmax = fmaxf(pmax, pm);
            has |= __shfl_down_sync(FULL, has, off);
        }

        if (lane == 0) {
            TaskRes r;
            r.s2 = S2; r.pmax = pmax; r.has = has;
            r.vfirst = sh.u.a.val[sh.order[0]];   // essential birth (global min)
            g_res[task] = r;
            __threadfence();
            unsigned old = atomicAdd(&g_ctr, 1u);
            if (old == NTASK - 1) {               // last block: compute the loss
                __threadfence();
                volatile TaskRes* gr = g_res;
                const int nfx[3] = {0, 0, 1};     // extra finite kept H0 pairs per class
                const int nf1[3] = {0, 1, 0};     // nf for H1 per class
                double loss = 0.0;
                for (int im = 0; im < 12; im++) {
                    int ci = im % 3;
                    double s2a = gr[im*2].s2;   float pma = gr[im*2].pmax;
                    int    ha  = gr[im*2].has;  float vf  = gr[im*2].vfirst;
                    double s2b = gr[im*2+1].s2; float pmb = gr[im*2+1].pmax;
                    int    hb  = gr[im*2+1].has;
                    double h0 = (double)vf * (double)vf + s2a;
                    if (nfx[ci]) {
                        if (ha) { double p = pma; h0 += (1.0-p)*(1.0-p) - p*p; }
                        else     h0 += 1.0;
                    }
                    double h1 = s2b;
                    if (nf1[ci]) {
                        if (hb) { double p = pmb; h1 += (1.0-p)*(1.0-p) - p*p; }
                        else     h1 += 1.0;
                    }
                    loss += h0 + h1;
                }
                out[0] = (float)(loss * 0.25);
                atomicSub(&g_ctr, (unsigned)NTASK);   // reset for next launch
            }
        }
    }
}

extern "C" void kernel_launch(void* const* d_in, const int* in_sizes, int n_in,
                              void* d_out, int out_size)
{
    (void)in_sizes; (void)n_in; (void)out_size;
    const float* x = (const float*)d_in[0];
    cudaFuncSetAttribute(uf_kernel, cudaFuncAttributeMaxDynamicSharedMemorySize,
                         (int)sizeof(Shm));
    uf_kernel<<<NTASK, BT, sizeof(Shm)>>>(x, (float*)d_out);
}